// round 14
// baseline (speedup 1.0000x reference)
#include <cuda_runtime.h>
#include <stdint.h>

// Problem constants (fixed by the reference: B=4, S=4096, D=2, 3 RK2 steps)
#define BB    4
#define SS    4096
#define WPR   (SS / 32)            // 128 bitmask words per row
#define NWRDS (BB * SS * WPR)      // 8 MB bitmask
#define NROWS (BB * SS)            // 16384 rows
#define CAP   80                   // padded index capacity (mean 41, sd 6.4; 6 sigma)
#define PS    (SS + 8)             // padded per-batch stride (float2 elems)
#define SENT  SS                   // sentinel index -> zero pad slot (in smem)
#define DT_F      0.1f
#define HALF_DT_F 0.05f
#define EPS_F     1e-8f

// Eval tiling: 8 threads per row, 128 rows per block (1024 threads, 128 blocks).
#define T_PER_ROW 8
#define IPT       (CAP / T_PER_ROW)   // 10 indices per thread
#define WPT       (WPR / T_PER_ROW)   // 16 bitmask words per thread (fallback)
#define ROWS_PB   128
#define ETPB      (ROWS_PB * T_PER_ROW)   // 1024 threads
#define EGRID     (NROWS / ROWS_PB)       // 128 blocks
#define STATE_BYTES (SS * 8)              // 32 KB staged per block

// Bitmask bit convention (OURS, not lane-major!):
//   word W = 4*i + k  (i = 0..31, k = 0..3), bit b  <->  column 128*i + 4*b + k

// ---- scratch (static device globals; no runtime allocation) ----
__device__ __align__(16) uint32_t       g_bits[NWRDS];
__device__ __align__(16) unsigned short g_idx[NROWS * CAP];   // sentinel-padded CSR
__device__               int            g_cnt[NROWS];         // true nnz per row
__device__ __align__(16) float2         g_ps[BB * PS];        // state p (padded stride)
__device__ __align__(16) float2         g_sp[BB * PS];        // psi_star
__device__ __align__(16) float2         g_k1[NROWS];
__device__               float          g_r[NROWS];

// ============================================================================
// 1) MERGED front: compress mask -> bitmask, build CSR indices, AND compute
//    step-1 evalA — one DRAM-bound pass over the 256 MB mask. 1 warp per row.
//    (Measured ~92% of HBM spec — at the roofline; unchanged.)
// ============================================================================
__global__ void __launch_bounds__(256)
fused_compress_evalA1(const float* __restrict__ mask,
                      const float2* __restrict__ psi) {
    const int lane = threadIdx.x & 31;
    const int row  = (blockIdx.x * blockDim.x + threadIdx.x) >> 5;  // 1 warp / row
    const int b    = row >> 12;
    const int pos  = row & (SS - 1);

    const float4* __restrict__ mrow =
        reinterpret_cast<const float4*>(mask + (size_t)row * SS);

    uint4 myw;
#pragma unroll
    for (int i = 0; i < 32; i++) {
        float4 v = mrow[i * 32 + lane];   // coalesced 512B per warp-iter
        unsigned b0 = __ballot_sync(0xFFFFFFFFu, v.x != 0.0f);
        unsigned b1 = __ballot_sync(0xFFFFFFFFu, v.y != 0.0f);
        unsigned b2 = __ballot_sync(0xFFFFFFFFu, v.z != 0.0f);
        unsigned b3 = __ballot_sync(0xFFFFFFFFu, v.w != 0.0f);
        if (lane == i) { myw.x = b0; myw.y = b1; myw.z = b2; myw.w = b3; }
    }

    reinterpret_cast<uint4*>(g_bits + (size_t)row * WPR)[lane] = myw;

    const int n = __popc(myw.x) + __popc(myw.y) + __popc(myw.z) + __popc(myw.w);
    int pfx = n;
#pragma unroll
    for (int off = 1; off < 32; off <<= 1) {
        int v = __shfl_up_sync(0xFFFFFFFFu, pfx, off);
        if (lane >= off) pfx += v;
    }
    const int total = __shfl_sync(0xFFFFFFFFu, pfx, 31);
    pfx -= n;  // exclusive
    if (lane == 0) g_cnt[row] = total;

    unsigned short* __restrict__ dst  = g_idx + (size_t)row * CAP;
    const float2*   __restrict__ psib = psi + (size_t)b * SS;

    float ax = 0.0f, ay = 0.0f;
    int slot = pfx;
    uint32_t ws[4] = {myw.x, myw.y, myw.z, myw.w};
#pragma unroll
    for (int k = 0; k < 4; k++) {       // word W = 4*lane + k
        uint32_t w = ws[k];
        while (w) {
            int bp = __ffs(w) - 1;
            w &= (w - 1);
            int col = lane * 128 + 4 * bp + k;   // OUR bit convention
            float2 v = psib[col];
            ax += v.x;
            ay += v.y;
            if (slot < CAP) dst[slot] = (unsigned short)col;
            slot++;
        }
    }
    for (int i = (total < CAP ? total : CAP) + lane; i < CAP; i += 32)
        dst[i] = (unsigned short)SENT;

#pragma unroll
    for (int off = 16; off > 0; off >>= 1) {
        ax += __shfl_down_sync(0xFFFFFFFFu, ax, off);
        ay += __shfl_down_sync(0xFFFFFFFFu, ay, off);
    }
    if (lane == 0) {
        float2 pi = psib[pos];
        float  r  = sqrtf(pi.x * pi.x + pi.y * pi.y);
        float k1x = ax - pi.x;
        float k1y = ay - pi.y;
        float sx  = fmaf(DT_F, k1x, pi.x);
        float sy  = fmaf(DT_F, k1y, pi.y);
        float sn  = sqrtf(sx * sx + sy * sy);
        float sc  = r / (sn + EPS_F);
        g_sp[b * PS + pos] = make_float2(sx * sc, sy * sc);  // psi_star
        g_k1[row]          = make_float2(k1x, k1y);
        g_r[row]           = r;
        g_ps[b * PS + pos] = pi;                              // state copy
    }
}

// ============================================================================
// mbarrier + 1D bulk-copy helpers (single UBLKCP stages the whole 32 KB;
// zero LSU issue cost — this was the R13 bottleneck: 2048 LDGSTS x 8cyc).
// ============================================================================
__device__ __forceinline__ void mbar_init(uint32_t mb, uint32_t count) {
    asm volatile("mbarrier.init.shared.b64 [%0], %1;" :: "r"(mb), "r"(count) : "memory");
}
__device__ __forceinline__ void mbar_expect_tx(uint32_t mb, uint32_t bytes) {
    asm volatile("mbarrier.arrive.expect_tx.shared.b64 _, [%0], %1;"
                 :: "r"(mb), "r"(bytes) : "memory");
}
__device__ __forceinline__ void bulk_g2s(uint32_t s_dst, const void* g_src,
                                         uint32_t bytes, uint32_t mb) {
    asm volatile("cp.async.bulk.shared::cta.global.mbarrier::complete_tx::bytes "
                 "[%0], [%1], %2, [%3];"
                 :: "r"(s_dst), "l"(g_src), "r"(bytes), "r"(mb) : "memory");
}
__device__ __forceinline__ void mbar_wait_parity0(uint32_t mb) {
    asm volatile(
        "{\n\t"
        ".reg .pred P1;\n\t"
        "WAIT_%=:\n\t"
        "mbarrier.try_wait.parity.acquire.cta.shared::cta.b64 P1, [%0], 0, 0x989680;\n\t"
        "@P1 bra.uni DONE_%=;\n\t"
        "bra.uni WAIT_%=;\n\t"
        "DONE_%=:\n\t"
        "}"
        :: "r"(mb) : "memory");
}

// ============================================================================
// Gather core. Indices/cnt are loaded UNDER the bulk-copy latency.
// ============================================================================
struct GatherCtx {
    int id[IPT];
    int cnt;
};

__device__ __forceinline__ void load_indices(GatherCtx& c, int row, int t) {
    c.cnt = g_cnt[row];
    const uint32_t* p32 = reinterpret_cast<const uint32_t*>(
        g_idx + (size_t)row * CAP + t * IPT);   // t*10 u16 = 20B -> 4B aligned
    uint32_t a0 = p32[0], a1 = p32[1], a2 = p32[2], a3 = p32[3], a4 = p32[4];
    c.id[0] = (int)(a0 & 0xFFFFu);  c.id[1] = (int)(a0 >> 16);
    c.id[2] = (int)(a1 & 0xFFFFu);  c.id[3] = (int)(a1 >> 16);
    c.id[4] = (int)(a2 & 0xFFFFu);  c.id[5] = (int)(a2 >> 16);
    c.id[6] = (int)(a3 & 0xFFFFu);  c.id[7] = (int)(a3 >> 16);
    c.id[8] = (int)(a4 & 0xFFFFu);  c.id[9] = (int)(a4 >> 16);
}

__device__ __forceinline__ void gather_reduce(const GatherCtx& c,
                                              const float2* __restrict__ sp,
                                              int row, int t,
                                              float& ax, float& ay) {
    ax = 0.0f; ay = 0.0f;
    if (c.cnt <= CAP) {
#pragma unroll
        for (int j = 0; j < IPT; j++) {   // 10 unconditional LDS.64
            float2 v = sp[c.id[j]];
            ax += v.x;
            ay += v.y;
        }
    } else {
        // Correctness fallback (cnt > CAP; ~6-sigma rare). Bitmask scan.
        const uint32_t* wr = g_bits + (size_t)row * WPR + t * WPT;
#pragma unroll
        for (int q = 0; q < WPT; q++) {
            int W = t * WPT + q;
            int i = W >> 2, k = W & 3;
            uint32_t w = wr[q];
            while (w) {
                int bp = __ffs(w) - 1;
                w &= (w - 1);
                float2 v = sp[128 * i + 4 * bp + k];
                ax += v.x;
                ay += v.y;
            }
        }
    }
#pragma unroll
    for (int off = T_PER_ROW / 2; off > 0; off >>= 1) {
        ax += __shfl_down_sync(0xFFFFFFFFu, ax, off, T_PER_ROW);
        ay += __shfl_down_sync(0xFFFFFFFFu, ay, off, T_PER_ROW);
    }
}

// ============================================================================
// 2) evalA: k1 = force(p); psi_star = renorm(p + dt*k1). Bulk-stages g_ps.
// ============================================================================
__global__ void __launch_bounds__(ETPB)
evalA_kernel() {
    __shared__ __align__(16) float2  sp[SS + 2];
    __shared__ __align__(8)  uint64_t mbar;

    const int tid = threadIdx.x;
    const int row = blockIdx.x * ROWS_PB + (tid >> 3);
    const int t   = tid & 7;
    const int b   = row >> 12;            // uniform per block (128 | 4096)
    const int pos = row & (SS - 1);

    const uint32_t mb = (uint32_t)__cvta_generic_to_shared(&mbar);
    if (tid == 0) mbar_init(mb, 1);

    GatherCtx c;
    load_indices(c, row, t);              // L2 loads overlap barrier setup

    __syncthreads();                      // mbar initialized before anyone waits
    if (tid == 0) {
        mbar_expect_tx(mb, STATE_BYTES);
        bulk_g2s((uint32_t)__cvta_generic_to_shared(sp),
                 g_ps + b * PS, STATE_BYTES, mb);
        sp[SS] = make_float2(0.0f, 0.0f);   // sentinel slot (outside bulk range)
    }

    mbar_wait_parity0(mb);
    __syncthreads();

    float ax, ay;
    gather_reduce(c, sp, row, t, ax, ay);

    if (t == 0) {
        float2 pi = sp[pos];
        float  r  = sqrtf(pi.x * pi.x + pi.y * pi.y);
        float k1x = ax - pi.x;
        float k1y = ay - pi.y;
        float sx  = fmaf(DT_F, k1x, pi.x);
        float sy  = fmaf(DT_F, k1y, pi.y);
        float sn  = sqrtf(sx * sx + sy * sy);
        float sc  = r / (sn + EPS_F);
        g_sp[b * PS + pos] = make_float2(sx * sc, sy * sc);
        g_k1[row]          = make_float2(k1x, k1y);
        g_r[row]           = r;
    }
}

// ============================================================================
// 3) evalB: k2 = force(psi_star); p = renorm(p + dt/2*(k1+k2)). Bulk-stages g_sp.
//    out == nullptr -> write g_ps; else write final result to out.
// ============================================================================
__global__ void __launch_bounds__(ETPB)
evalB_kernel(float2* __restrict__ out) {
    __shared__ __align__(16) float2  sp[SS + 2];
    __shared__ __align__(8)  uint64_t mbar;

    const int tid = threadIdx.x;
    const int row = blockIdx.x * ROWS_PB + (tid >> 3);
    const int t   = tid & 7;
    const int b   = row >> 12;
    const int pos = row & (SS - 1);

    const uint32_t mb = (uint32_t)__cvta_generic_to_shared(&mbar);
    if (tid == 0) mbar_init(mb, 1);

    GatherCtx c;
    load_indices(c, row, t);

    // t==0 auxiliary operands, hidden under the bulk-copy latency.
    float2 k1 = make_float2(0.f, 0.f), p = make_float2(0.f, 0.f);
    float  r  = 0.f;
    if (t == 0) {
        k1 = g_k1[row];
        p  = g_ps[b * PS + pos];
        r  = g_r[row];
    }

    __syncthreads();
    if (tid == 0) {
        mbar_expect_tx(mb, STATE_BYTES);
        bulk_g2s((uint32_t)__cvta_generic_to_shared(sp),
                 g_sp + b * PS, STATE_BYTES, mb);
        sp[SS] = make_float2(0.0f, 0.0f);
    }

    mbar_wait_parity0(mb);
    __syncthreads();

    float ax, ay;
    gather_reduce(c, sp, row, t, ax, ay);

    if (t == 0) {
        float2 si = sp[pos];
        float k2x = ax - si.x;
        float k2y = ay - si.y;
        float nx  = fmaf(HALF_DT_F, k1.x + k2x, p.x);
        float ny  = fmaf(HALF_DT_F, k1.y + k2y, p.y);
        float nn  = sqrtf(nx * nx + ny * ny);
        float sc  = r / (nn + EPS_F);
        float2 res = make_float2(nx * sc, ny * sc);
        if (out) out[row]           = res;
        else     g_ps[b * PS + pos] = res;
    }
}

// ============================================================================
// Launch: merged front kernel + 5 bulk-staged evals. All graph-capturable.
// ============================================================================
extern "C" void kernel_launch(void* const* d_in, const int* in_sizes, int n_in,
                              void* d_out, int out_size) {
    const float* psi  = (const float*)d_in[0];
    const float* mask = (const float*)d_in[1];
    if (n_in >= 2 && in_sizes[0] > in_sizes[1]) {  // defensive: pick by size
        psi  = (const float*)d_in[1];
        mask = (const float*)d_in[0];
    }

    // Step 1 evalA fused with compression + index build (1 warp per row).
    fused_compress_evalA1<<<NROWS / 8, 256>>>(mask, (const float2*)psi);

    // Remaining 5 force evals.
    evalB_kernel<<<EGRID, ETPB>>>(nullptr);        // step 1 B
    evalA_kernel<<<EGRID, ETPB>>>();               // step 2 A
    evalB_kernel<<<EGRID, ETPB>>>(nullptr);        // step 2 B
    evalA_kernel<<<EGRID, ETPB>>>();               // step 3 A
    evalB_kernel<<<EGRID, ETPB>>>((float2*)d_out); // step 3 B -> output

    (void)out_size;
}